// round 1
// baseline (speedup 1.0000x reference)
#include <cuda_runtime.h>
#include <cstdint>

#define BB 4
#define CC 64
#define HH 48
#define WW 64
#define NN (HH*WW)        // 3072
#define BM 128
#define BN 128
#define NTILE (NN/BM)     // 24
#define ROWP 132          // padded row stride (floats) for smem tiles

// ---------------- device scratch (static: no allocations allowed) ----------------
__device__ float g_srcT[BB*NN*CC];   // (B, H*W, C) transposed source images
__device__ float g_tgtT[BB*NN*CC];
__device__ float g_sd[BB*NN*CC];     // sampled+normalized source descriptors (B,N,C)
__device__ float g_td[BB*NN*CC];
__device__ unsigned long long g_row_all[BB*NN];  // per src point: max dot over all tgt
__device__ unsigned long long g_row_un [BB*NN];  // ... over unmasked tgt
__device__ unsigned long long g_col_all[BB*NN];  // per tgt point: max dot over all src
__device__ unsigned long long g_col_un [BB*NN];
__device__ float g_acc[2];           // [loss_sum, correct_sum]

// ---------------- key packing: argmax(dot) with first-index tie-break ----------------
__device__ __forceinline__ unsigned long long make_key(float f, int idx) {
    unsigned u = __float_as_uint(f);
    u = (u & 0x80000000u) ? ~u : (u | 0x80000000u);  // order-preserving float->uint
    return ((unsigned long long)u << 32) | (unsigned)(0xFFFFFFFFu - (unsigned)idx);
}
__device__ __forceinline__ float key_dot(unsigned long long k) {
    unsigned u = (unsigned)(k >> 32);
    return (u & 0x80000000u) ? __uint_as_float(u ^ 0x80000000u) : __uint_as_float(~u);
}
__device__ __forceinline__ int key_idx(unsigned long long k) {
    return (int)(0xFFFFFFFFu - (unsigned)(k & 0xFFFFFFFFu));
}
__device__ __forceinline__ float dist_from_dot(float d) {
    d = fminf(fmaxf(d, -1.f), 1.f);
    return sqrtf(fmaxf(2.f - 2.f*d, 0.f));
}

// ---------------- 1. transpose (B,C,H,W) -> (B, H*W, C) ----------------
__global__ void transpose_kernel(const float* __restrict__ src, const float* __restrict__ tgt) {
    const int T = BB*CC*NN;
    int i = blockIdx.x*blockDim.x + threadIdx.x;
    if (i >= 2*T) return;
    const float* in; float* out;
    int j = i;
    if (j < T) { in = src; out = g_srcT; } else { j -= T; in = tgt; out = g_tgtT; }
    int p = j % NN;
    int c = (j / NN) % CC;
    int b = j / (NN*CC);
    out[((size_t)b*NN + p)*CC + c] = in[j];
}

// ---------------- 2. zero reductions/accumulators ----------------
__global__ void init_kernel() {
    int i = blockIdx.x*blockDim.x + threadIdx.x;
    if (i < BB*NN) {
        g_row_all[i] = 0ULL; g_row_un[i] = 0ULL;
        g_col_all[i] = 0ULL; g_col_un[i] = 0ULL;
    }
    if (i < 2) g_acc[i] = 0.f;
}

// ---------------- 3. bilinear sample + L2 normalize (warp per point/side) ----------------
__global__ void sample_kernel(const float* __restrict__ spn, const float* __restrict__ tpn) {
    int gw   = (blockIdx.x*blockDim.x + threadIdx.x) >> 5;   // global warp id
    int lane = threadIdx.x & 31;
    // gw in [0, B*2*N)
    int b    = gw / (2*NN);
    int rem  = gw - b*2*NN;
    int side = rem / NN;       // 0 = source, 1 = target
    int p    = rem - side*NN;

    const float* g = (side ? tpn : spn) + ((size_t)b*NN + p)*2;
    float gx = g[0], gy = g[1];
    const float* img = (side ? g_tgtT : g_srcT) + (size_t)b*NN*CC;

    float x = ((gx + 1.f)*WW - 1.f)*0.5f;
    float y = ((gy + 1.f)*HH - 1.f)*0.5f;
    float x0f = floorf(x), y0f = floorf(y);
    int x0 = (int)x0f, y0 = (int)y0f;
    int x1 = x0 + 1,   y1 = y0 + 1;
    float wx1 = x - x0f, wx0 = 1.f - wx1;
    float wy1 = y - y0f, wy0 = 1.f - wy1;

    float v0 = 0.f, v1 = 0.f;
    #define CORNER(XI, YI, WGT) do { \
        if ((XI) >= 0 && (XI) < WW && (YI) >= 0 && (YI) < HH) { \
            const float* q = img + ((size_t)(YI)*WW + (XI))*CC; \
            v0 += (WGT)*q[lane]; v1 += (WGT)*q[lane+32]; \
        } } while(0)
    CORNER(x0, y0, wx0*wy0);
    CORNER(x1, y0, wx1*wy0);
    CORNER(x0, y1, wx0*wy1);
    CORNER(x1, y1, wx1*wy1);
    #undef CORNER

    float ss = v0*v0 + v1*v1;
    #pragma unroll
    for (int m = 16; m; m >>= 1) ss += __shfl_xor_sync(0xFFFFFFFFu, ss, m);
    float inv = 1.f / fmaxf(sqrtf(ss), 1e-12f);

    float* out = (side ? g_td : g_sd) + ((size_t)b*NN + p)*CC;
    out[lane]      = v0*inv;
    out[lane + 32] = v1*inv;
}

// ---------------- 4. tiled GEMM + fused row/col argmax reductions ----------------
__global__ void __launch_bounds__(256) gemm_reduce_kernel(const float* __restrict__ tpu,
                                                          const int* __restrict__ rf) {
    __shared__ float As[32*ROWP];    // [k][row], k-chunk of 32
    __shared__ float Bs[32*ROWP];    // [k][col]
    __shared__ float pxr[128], pyr[128], pxc[128], pyc[128];
    __shared__ unsigned long long s_r_all[128], s_r_un[128], s_c_all[128], s_c_un[128];

    int b       = blockIdx.z;
    int rowBase = blockIdx.y * BM;
    int colBase = blockIdx.x * BN;
    int tid     = threadIdx.x;

    // relax_field: robust to int32 or float32 encoding
    int rv = rf[0];
    float relax = (rv >= 0 && rv < 1000000) ? (float)rv : __int_as_float(rv);

    const float* A  = g_sd + ((size_t)b*NN + rowBase)*CC;
    const float* Bp = g_td + ((size_t)b*NN + colBase)*CC;

    if (tid < 128) {
        const float* px = tpu + (size_t)b*2*NN;
        const float* py = px + NN;
        pxr[tid] = px[rowBase + tid]; pyr[tid] = py[rowBase + tid];
        pxc[tid] = px[colBase + tid]; pyc[tid] = py[colBase + tid];
        s_r_all[tid] = 0ULL; s_r_un[tid] = 0ULL;
        s_c_all[tid] = 0ULL; s_c_un[tid] = 0ULL;
    }

    int tr = tid >> 4, tc = tid & 15;
    int r0 = tr*8, c0 = tc*8;
    float acc[8][8];
    #pragma unroll
    for (int ii = 0; ii < 8; ii++)
        #pragma unroll
        for (int jj = 0; jj < 8; jj++) acc[ii][jj] = 0.f;

    // two K-chunks of 32 (keeps static smem < 48KB)
    for (int kc = 0; kc < 2; kc++) {
        __syncthreads();
        #pragma unroll
        for (int q = 0; q < 4; q++) {
            int id  = tid + q*256;       // 0..1023: 128 rows x 8 float4
            int row = id >> 3;
            int k4  = id & 7;
            int kk  = k4*4;
            float4 va = *(const float4*)(A  + (size_t)row*CC + kc*32 + kk);
            float4 vb = *(const float4*)(Bp + (size_t)row*CC + kc*32 + kk);
            As[(kk+0)*ROWP + row] = va.x; As[(kk+1)*ROWP + row] = va.y;
            As[(kk+2)*ROWP + row] = va.z; As[(kk+3)*ROWP + row] = va.w;
            Bs[(kk+0)*ROWP + row] = vb.x; Bs[(kk+1)*ROWP + row] = vb.y;
            Bs[(kk+2)*ROWP + row] = vb.z; Bs[(kk+3)*ROWP + row] = vb.w;
        }
        __syncthreads();
        #pragma unroll 8
        for (int k = 0; k < 32; k++) {
            float av[8], bv[8];
            float4 t0 = *(const float4*)&As[k*ROWP + r0];
            float4 t1 = *(const float4*)&As[k*ROWP + r0 + 4];
            float4 u0 = *(const float4*)&Bs[k*ROWP + c0];
            float4 u1 = *(const float4*)&Bs[k*ROWP + c0 + 4];
            av[0]=t0.x; av[1]=t0.y; av[2]=t0.z; av[3]=t0.w;
            av[4]=t1.x; av[5]=t1.y; av[6]=t1.z; av[7]=t1.w;
            bv[0]=u0.x; bv[1]=u0.y; bv[2]=u0.z; bv[3]=u0.w;
            bv[4]=u1.x; bv[5]=u1.y; bv[6]=u1.z; bv[7]=u1.w;
            #pragma unroll
            for (int ii = 0; ii < 8; ii++)
                #pragma unroll
                for (int jj = 0; jj < 8; jj++)
                    acc[ii][jj] = fmaf(av[ii], bv[jj], acc[ii][jj]);
        }
    }

    // row-wise (st direction) partial argmax
    #pragma unroll
    for (int ii = 0; ii < 8; ii++) {
        int lr = r0 + ii;
        float prx = pxr[lr], pry = pyr[lr];
        unsigned long long ba = 0ULL, bu = 0ULL;
        #pragma unroll
        for (int jj = 0; jj < 8; jj++) {
            int lc = c0 + jj;
            unsigned long long key = make_key(acc[ii][jj], colBase + lc);
            if (key > ba) ba = key;
            bool m = (fabsf(pxc[lc]-prx) <= relax) && (fabsf(pyc[lc]-pry) <= relax);
            if (!m && key > bu) bu = key;
        }
        atomicMax(&s_r_all[lr], ba);
        if (bu) atomicMax(&s_r_un[lr], bu);
    }
    // col-wise (ts direction) partial argmax
    #pragma unroll
    for (int jj = 0; jj < 8; jj++) {
        int lc = c0 + jj;
        float pcx = pxc[lc], pcy = pyc[lc];
        unsigned long long ba = 0ULL, bu = 0ULL;
        #pragma unroll
        for (int ii = 0; ii < 8; ii++) {
            int lr = r0 + ii;
            unsigned long long key = make_key(acc[ii][jj], rowBase + lr);
            if (key > ba) ba = key;
            bool m = (fabsf(pxr[lr]-pcx) <= relax) && (fabsf(pyr[lr]-pcy) <= relax);
            if (!m && key > bu) bu = key;
        }
        atomicMax(&s_c_all[lc], ba);
        if (bu) atomicMax(&s_c_un[lc], bu);
    }
    __syncthreads();
    if (tid < 128) {
        atomicMax(&g_row_all[(size_t)b*NN + rowBase + tid], s_r_all[tid]);
        if (s_r_un[tid]) atomicMax(&g_row_un[(size_t)b*NN + rowBase + tid], s_r_un[tid]);
        atomicMax(&g_col_all[(size_t)b*NN + colBase + tid], s_c_all[tid]);
        if (s_c_un[tid]) atomicMax(&g_col_un[(size_t)b*NN + colBase + tid], s_c_un[tid]);
    }
}

// ---------------- 5. triplet loss + recall (warp per anchor point) ----------------
__global__ void finalize_kernel(const float* __restrict__ tpu) {
    __shared__ float s_loss[8], s_corr[8];
    int gw   = (blockIdx.x*blockDim.x + threadIdx.x) >> 5;   // in [0, B*N)
    int lane = threadIdx.x & 31;
    int warp = threadIdx.x >> 5;

    int b = gw / NN;
    int i = gw - b*NN;
    const float* px = tpu + (size_t)b*2*NN;
    const float* py = px + NN;
    size_t base = (size_t)b*NN + i;

    unsigned long long kra = g_row_all[base];
    unsigned long long kru = g_row_un [base];
    unsigned long long kca = g_col_all[base];
    unsigned long long kcu = g_col_un [base];

    int nn_st = key_idx(kra);
    int nn_ts = key_idx(kca);
    int neg_st, neg_ts;
    float d_st, d_ts;
    if (kru == 0ULL) { neg_st = 0; d_st = 2.f; }
    else { neg_st = key_idx(kru); d_st = dist_from_dot(key_dot(kru)); }
    if (kcu == 0ULL) { neg_ts = 0; d_ts = 2.f; }
    else { neg_ts = key_idx(kcu); d_ts = dist_from_dot(key_dot(kcu)); }

    bool take_ts = d_ts < d_st;   // ties -> st, matching reference
    const float* a = (take_ts ? g_td : g_sd) + base*CC;
    const float* p = (take_ts ? g_sd : g_td) + base*CC;
    const float* n = take_ts ? (g_sd + ((size_t)b*NN + neg_ts)*CC)
                             : (g_td + ((size_t)b*NN + neg_st)*CC);

    float dp2 = 0.f, dn2 = 0.f;
    #pragma unroll
    for (int c = lane; c < CC; c += 32) {
        float av = a[c];
        float e1 = av - p[c] + 1e-6f; dp2 = fmaf(e1, e1, dp2);
        float e2 = av - n[c] + 1e-6f; dn2 = fmaf(e2, e2, dn2);
    }
    #pragma unroll
    for (int m = 16; m; m >>= 1) {
        dp2 += __shfl_xor_sync(0xFFFFFFFFu, dp2, m);
        dn2 += __shfl_xor_sync(0xFFFFFFFFu, dn2, m);
    }
    if (lane == 0) {
        float loss = fmaxf(sqrtf(dp2) - sqrtf(dn2) + 0.2f, 0.f);
        float corr = 0.f;
        float pxi = px[i], pyi = py[i];
        if (px[nn_st] == pxi && py[nn_st] == pyi) corr += 1.f;
        if (px[nn_ts] == pxi && py[nn_ts] == pyi) corr += 1.f;
        s_loss[warp] = loss;
        s_corr[warp] = corr;
    }
    __syncthreads();
    if (threadIdx.x == 0) {
        float L = 0.f, Cr = 0.f;
        #pragma unroll
        for (int w = 0; w < 8; w++) { L += s_loss[w]; Cr += s_corr[w]; }
        atomicAdd(&g_acc[0], L);
        atomicAdd(&g_acc[1], Cr);
    }
}

// ---------------- 6. write outputs ----------------
__global__ void writeout_kernel(float* __restrict__ out) {
    out[0] = g_acc[0] / (float)(BB*NN);        // loss.mean()
    out[1] = g_acc[1] / (float)(2*BB*NN);      // recall.mean()
}

// ---------------- launch ----------------
extern "C" void kernel_launch(void* const* d_in, const int* in_sizes, int n_in,
                              void* d_out, int out_size) {
    const float* src = (const float*)d_in[0];   // source_des     (B,C,H,W)
    const float* tgt = (const float*)d_in[1];   // target_des     (B,C,H,W)
    const float* spn = (const float*)d_in[2];   // source_points_norm (B,H,W,2)
    const float* tpn = (const float*)d_in[3];   // target_points_norm (B,H,W,2)
    const float* tpu = (const float*)d_in[4];   // target_points_unnorm (B,2,H,W)
    const int*   rf  = (const int*)  d_in[5];   // relax_field
    float* out = (float*)d_out;

    const int T2 = 2*BB*CC*NN;
    transpose_kernel<<<(T2 + 255)/256, 256>>>(src, tgt);
    init_kernel<<<(BB*NN + 255)/256, 256>>>();
    sample_kernel<<<(BB*2*NN)/8, 256>>>(spn, tpn);

    dim3 grid(NTILE, NTILE, BB);
    gemm_reduce_kernel<<<grid, 256>>>(tpu, rf);

    finalize_kernel<<<(BB*NN)/8, 256>>>(tpu);
    writeout_kernel<<<1, 1>>>(out);
}

// round 4
// speedup vs baseline: 1.1151x; 1.1151x over previous
#include <cuda_runtime.h>
#include <cstdint>

#define BB 4
#define CC 64
#define HH 48
#define WW 64
#define NN (HH*WW)        // 3072
#define BM 128
#define BN 128
#define NTILE (NN/BM)     // 24
#define KC 32             // k-chunk
#define LDA 36            // padded smem row stride (floats): conflict-free frag loads

// ---------------- device scratch ----------------
__device__ float g_srcT[BB*NN*CC];
__device__ float g_tgtT[BB*NN*CC];
__device__ float g_sd[BB*NN*CC];
__device__ float g_td[BB*NN*CC];
__device__ unsigned long long g_row_all[BB*NN];
__device__ unsigned long long g_row_un [BB*NN];
__device__ unsigned long long g_col_all[BB*NN];
__device__ unsigned long long g_col_un [BB*NN];
__device__ float g_acc[2];

// ---------------- key packing: argmax(dot), first-index tie-break ----------------
__device__ __forceinline__ unsigned long long make_key(float f, int idx) {
    unsigned u = __float_as_uint(f);
    u = (u & 0x80000000u) ? ~u : (u | 0x80000000u);
    return ((unsigned long long)u << 32) | (unsigned)(0xFFFFFFFFu - (unsigned)idx);
}
__device__ __forceinline__ float key_dot(unsigned long long k) {
    unsigned u = (unsigned)(k >> 32);
    return (u & 0x80000000u) ? __uint_as_float(u ^ 0x80000000u) : __uint_as_float(~u);
}
__device__ __forceinline__ int key_idx(unsigned long long k) {
    return (int)(0xFFFFFFFFu - (unsigned)(k & 0xFFFFFFFFu));
}
__device__ __forceinline__ float dist_from_dot(float d) {
    d = fminf(fmaxf(d, -1.f), 1.f);
    return sqrtf(fmaxf(2.f - 2.f*d, 0.f));
}
__device__ __forceinline__ unsigned f2tf32(float x) {
    unsigned r;
    asm("cvt.rna.tf32.f32 %0, %1;" : "=r"(r) : "f"(x));
    return r;
}
__device__ __forceinline__ void mma_tf32(float* c, unsigned a0, unsigned a1,
                                         unsigned a2, unsigned a3,
                                         unsigned b0, unsigned b1) {
    asm volatile(
        "mma.sync.aligned.m16n8k8.row.col.f32.tf32.tf32.f32 "
        "{%0,%1,%2,%3}, {%4,%5,%6,%7}, {%8,%9}, {%0,%1,%2,%3};\n"
        : "+f"(c[0]), "+f"(c[1]), "+f"(c[2]), "+f"(c[3])
        : "r"(a0), "r"(a1), "r"(a2), "r"(a3), "r"(b0), "r"(b1));
}

// ---------------- 1. transpose (B,C,H,W) -> (B,H*W,C), fused init ----------------
__global__ void transpose_kernel(const float* __restrict__ src, const float* __restrict__ tgt) {
    const int T = BB*CC*NN;
    int i = blockIdx.x*blockDim.x + threadIdx.x;
    if (i < 2*T) {
        const float* in; float* out;
        int j = i;
        if (j < T) { in = src; out = g_srcT; } else { j -= T; in = tgt; out = g_tgtT; }
        int p = j % NN;
        int c = (j / NN) % CC;
        int b = j / (NN*CC);
        out[((size_t)b*NN + p)*CC + c] = in[j];
    }
    // fused init of reduction buffers + accumulators
    if (i < BB*NN) {
        g_row_all[i] = 0ULL; g_row_un[i] = 0ULL;
        g_col_all[i] = 0ULL; g_col_un[i] = 0ULL;
    }
    if (i < 2) g_acc[i] = 0.f;
}

// ---------------- 3. bilinear sample + normalize ----------------
__global__ void sample_kernel(const float* __restrict__ spn, const float* __restrict__ tpn) {
    int gw   = (blockIdx.x*blockDim.x + threadIdx.x) >> 5;
    int lane = threadIdx.x & 31;
    int b    = gw / (2*NN);
    int rem  = gw - b*2*NN;
    int side = rem / NN;
    int p    = rem - side*NN;

    const float* g = (side ? tpn : spn) + ((size_t)b*NN + p)*2;
    float gx = g[0], gy = g[1];
    const float* img = (side ? g_tgtT : g_srcT) + (size_t)b*NN*CC;

    float x = ((gx + 1.f)*WW - 1.f)*0.5f;
    float y = ((gy + 1.f)*HH - 1.f)*0.5f;
    float x0f = floorf(x), y0f = floorf(y);
    int x0 = (int)x0f, y0 = (int)y0f;
    int x1 = x0 + 1,   y1 = y0 + 1;
    float wx1 = x - x0f, wx0 = 1.f - wx1;
    float wy1 = y - y0f, wy0 = 1.f - wy1;

    float v0 = 0.f, v1 = 0.f;
    #define CORNER(XI, YI, WGT) do { \
        if ((XI) >= 0 && (XI) < WW && (YI) >= 0 && (YI) < HH) { \
            const float* q = img + ((size_t)(YI)*WW + (XI))*CC; \
            v0 += (WGT)*q[lane]; v1 += (WGT)*q[lane+32]; \
        } } while(0)
    CORNER(x0, y0, wx0*wy0);
    CORNER(x1, y0, wx1*wy0);
    CORNER(x0, y1, wx0*wy1);
    CORNER(x1, y1, wx1*wy1);
    #undef CORNER

    float ss = v0*v0 + v1*v1;
    #pragma unroll
    for (int m = 16; m; m >>= 1) ss += __shfl_xor_sync(0xFFFFFFFFu, ss, m);
    float inv = 1.f / fmaxf(sqrtf(ss), 1e-12f);

    float* out = (side ? g_td : g_sd) + ((size_t)b*NN + p)*CC;
    out[lane]      = v0*inv;
    out[lane + 32] = v1*inv;
}

// ---------------- 4. TF32x3 tensor-core GEMM + fused argmax reductions ----------------
__global__ void __launch_bounds__(256) gemm_reduce_kernel(const float* __restrict__ tpu,
                                                          const int* __restrict__ rf) {
    __shared__ float As[BM*LDA];
    __shared__ float Bs[BN*LDA];
    __shared__ float pxr[BM], pyr[BM], pxc[BN], pyc[BN];
    __shared__ unsigned long long s_r_all[BM], s_r_un[BM], s_c_all[BN], s_c_un[BN];

    const int b       = blockIdx.z;
    const int rowBase = blockIdx.y * BM;
    const int colBase = blockIdx.x * BN;
    const int tid     = threadIdx.x;
    const int wid     = tid >> 5;
    const int lane    = tid & 31;
    const int gid     = lane >> 2;   // group id 0..7
    const int tig     = lane & 3;    // thread in group 0..3

    int rv = rf[0];
    float relax = (rv >= 0 && rv < 1000000) ? (float)rv : __int_as_float(rv);

    // warp tiling: 2 warps along M (64 rows each), 4 along N (32 cols each)
    const int rowW = (wid & 1) * 64;
    const int colW = (wid >> 1) * 32;

    const float* A  = g_sd + ((size_t)b*NN + rowBase)*CC;
    const float* Bp = g_td + ((size_t)b*NN + colBase)*CC;

    if (tid < 128) {
        const float* px = tpu + (size_t)b*2*NN;
        const float* py = px + NN;
        pxr[tid] = px[rowBase + tid]; pyr[tid] = py[rowBase + tid];
        pxc[tid] = px[colBase + tid]; pyc[tid] = py[colBase + tid];
        s_r_all[tid] = 0ULL; s_r_un[tid] = 0ULL;
        s_c_all[tid] = 0ULL; s_c_un[tid] = 0ULL;
    }

    float acc[4][4][4];   // [mtile][ntile][c0..c3]
    #pragma unroll
    for (int mt = 0; mt < 4; mt++)
        #pragma unroll
        for (int nt = 0; nt < 4; nt++)
            #pragma unroll
            for (int e = 0; e < 4; e++) acc[mt][nt][e] = 0.f;

    #pragma unroll
    for (int kc = 0; kc < 2; kc++) {
        __syncthreads();
        #pragma unroll
        for (int q = 0; q < 4; q++) {
            int idx = tid + q*256;        // 0..1023
            int row = idx >> 3;
            int k4  = (idx & 7) * 4;
            float4 va = *(const float4*)(A  + (size_t)row*CC + kc*KC + k4);
            float4 vb = *(const float4*)(Bp + (size_t)row*CC + kc*KC + k4);
            *(float4*)&As[row*LDA + k4] = va;
            *(float4*)&Bs[row*LDA + k4] = vb;
        }
        __syncthreads();

        #pragma unroll
        for (int ks = 0; ks < 4; ks++) {
            const int kk = ks*8;
            // B fragments: 4 n-tiles x 2 regs, split hi/lo
            unsigned bh[4][2], bl[4][2];
            #pragma unroll
            for (int nt = 0; nt < 4; nt++) {
                int col = colW + nt*8 + gid;
                float v0 = Bs[col*LDA + kk + tig];
                float v1 = Bs[col*LDA + kk + tig + 4];
                unsigned h0 = f2tf32(v0), h1 = f2tf32(v1);
                bh[nt][0] = h0; bh[nt][1] = h1;
                bl[nt][0] = f2tf32(v0 - __uint_as_float(h0));
                bl[nt][1] = f2tf32(v1 - __uint_as_float(h1));
            }
            #pragma unroll
            for (int mt = 0; mt < 4; mt++) {
                int r0 = rowW + mt*16 + gid;
                float a0 = As[(r0    )*LDA + kk + tig];
                float a1 = As[(r0 + 8)*LDA + kk + tig];
                float a2 = As[(r0    )*LDA + kk + tig + 4];
                float a3 = As[(r0 + 8)*LDA + kk + tig + 4];
                unsigned ah0 = f2tf32(a0), ah1 = f2tf32(a1);
                unsigned ah2 = f2tf32(a2), ah3 = f2tf32(a3);
                unsigned al0 = f2tf32(a0 - __uint_as_float(ah0));
                unsigned al1 = f2tf32(a1 - __uint_as_float(ah1));
                unsigned al2 = f2tf32(a2 - __uint_as_float(ah2));
                unsigned al3 = f2tf32(a3 - __uint_as_float(ah3));
                #pragma unroll
                for (int nt = 0; nt < 4; nt++) {
                    mma_tf32(acc[mt][nt], ah0, ah1, ah2, ah3, bh[nt][0], bh[nt][1]);
                    mma_tf32(acc[mt][nt], ah0, ah1, ah2, ah3, bl[nt][0], bl[nt][1]);
                    mma_tf32(acc[mt][nt], al0, al1, al2, al3, bh[nt][0], bh[nt][1]);
                }
            }
        }
    }

    // ---- epilogue: row-wise (st) argmax; within-thread ascending idx keeps first ----
    #pragma unroll
    for (int mt = 0; mt < 4; mt++) {
        #pragma unroll
        for (int half = 0; half < 2; half++) {
            int r_loc = rowW + mt*16 + gid + half*8;
            float prx = pxr[r_loc], pry = pyr[r_loc];
            float va = -3.f, vu = -3.f;
            int   ia = 0,    iu = 0;
            #pragma unroll
            for (int nt = 0; nt < 4; nt++) {
                #pragma unroll
                for (int e = 0; e < 2; e++) {
                    int c_loc = colW + nt*8 + tig*2 + e;
                    float v = acc[mt][nt][half*2 + e];
                    int idx = colBase + c_loc;
                    if (v > va) { va = v; ia = idx; }
                    bool m = (fabsf(pxc[c_loc]-prx) <= relax) && (fabsf(pyc[c_loc]-pry) <= relax);
                    if (!m && v > vu) { vu = v; iu = idx; }
                }
            }
            #pragma unroll
            for (int s = 1; s <= 2; s <<= 1) {
                float ov = __shfl_xor_sync(0xFFFFFFFFu, va, s);
                int   oi = __shfl_xor_sync(0xFFFFFFFFu, ia, s);
                if (ov > va || (ov == va && oi < ia)) { va = ov; ia = oi; }
                float ow = __shfl_xor_sync(0xFFFFFFFFu, vu, s);
                int   oj = __shfl_xor_sync(0xFFFFFFFFu, iu, s);
                if (ow > vu || (ow == vu && oj < iu)) { vu = ow; iu = oj; }
            }
            if (tig == 0) {
                atomicMax(&s_r_all[r_loc], make_key(va, ia));
                if (vu > -2.5f) atomicMax(&s_r_un[r_loc], make_key(vu, iu));
            }
        }
    }
    // ---- col-wise (ts) argmax ----
    #pragma unroll
    for (int nt = 0; nt < 4; nt++) {
        #pragma unroll
        for (int e = 0; e < 2; e++) {
            int c_loc = colW + nt*8 + tig*2 + e;
            float pcx = pxc[c_loc], pcy = pyc[c_loc];
            float va = -3.f, vu = -3.f;
            int   ia = 0,    iu = 0;
            #pragma unroll
            for (int mt = 0; mt < 4; mt++) {
                #pragma unroll
                for (int half = 0; half < 2; half++) {
                    int r_loc = rowW + mt*16 + gid + half*8;
                    float v = acc[mt][nt][half*2 + e];
                    int idx = rowBase + r_loc;
                    if (v > va) { va = v; ia = idx; }
                    bool m = (fabsf(pxr[r_loc]-pcx) <= relax) && (fabsf(pyr[r_loc]-pcy) <= relax);
                    if (!m && v > vu) { vu = v; iu = idx; }
                }
            }
            #pragma unroll
            for (int s = 4; s <= 16; s <<= 1) {
                float ov = __shfl_xor_sync(0xFFFFFFFFu, va, s);
                int   oi = __shfl_xor_sync(0xFFFFFFFFu, ia, s);
                if (ov > va || (ov == va && oi < ia)) { va = ov; ia = oi; }
                float ow = __shfl_xor_sync(0xFFFFFFFFu, vu, s);
                int   oj = __shfl_xor_sync(0xFFFFFFFFu, iu, s);
                if (ow > vu || (ow == vu && oj < iu)) { vu = ow; iu = oj; }
            }
            if (gid == 0) {
                atomicMax(&s_c_all[c_loc], make_key(va, ia));
                if (vu > -2.5f) atomicMax(&s_c_un[c_loc], make_key(vu, iu));
            }
        }
    }
    __syncthreads();
    if (tid < 128) {
        atomicMax(&g_row_all[(size_t)b*NN + rowBase + tid], s_r_all[tid]);
        if (s_r_un[tid]) atomicMax(&g_row_un[(size_t)b*NN + rowBase + tid], s_r_un[tid]);
        atomicMax(&g_col_all[(size_t)b*NN + colBase + tid], s_c_all[tid]);
        if (s_c_un[tid]) atomicMax(&g_col_un[(size_t)b*NN + colBase + tid], s_c_un[tid]);
    }
}

// ---------------- 5. triplet loss + recall ----------------
__global__ void finalize_kernel(const float* __restrict__ tpu) {
    __shared__ float s_loss[8], s_corr[8];
    int gw   = (blockIdx.x*blockDim.x + threadIdx.x) >> 5;
    int lane = threadIdx.x & 31;
    int warp = threadIdx.x >> 5;

    int b = gw / NN;
    int i = gw - b*NN;
    const float* px = tpu + (size_t)b*2*NN;
    const float* py = px + NN;
    size_t base = (size_t)b*NN + i;

    unsigned long long kra = g_row_all[base];
    unsigned long long kru = g_row_un [base];
    unsigned long long kca = g_col_all[base];
    unsigned long long kcu = g_col_un [base];

    int nn_st = key_idx(kra);
    int nn_ts = key_idx(kca);
    int neg_st, neg_ts;
    float d_st, d_ts;
    if (kru == 0ULL) { neg_st = 0; d_st = 2.f; }
    else { neg_st = key_idx(kru); d_st = dist_from_dot(key_dot(kru)); }
    if (kcu == 0ULL) { neg_ts = 0; d_ts = 2.f; }
    else { neg_ts = key_idx(kcu); d_ts = dist_from_dot(key_dot(kcu)); }

    bool take_ts = d_ts < d_st;
    const float* a = (take_ts ? g_td : g_sd) + base*CC;
    const float* p = (take_ts ? g_sd : g_td) + base*CC;
    const float* n = take_ts ? (g_sd + ((size_t)b*NN + neg_ts)*CC)
                             : (g_td + ((size_t)b*NN + neg_st)*CC);

    float dp2 = 0.f, dn2 = 0.f;
    #pragma unroll
    for (int c = lane; c < CC; c += 32) {
        float av = a[c];
        float e1 = av - p[c] + 1e-6f; dp2 = fmaf(e1, e1, dp2);
        float e2 = av - n[c] + 1e-6f; dn2 = fmaf(e2, e2, dn2);
    }
    #pragma unroll
    for (int m = 16; m; m >>= 1) {
        dp2 += __shfl_xor_sync(0xFFFFFFFFu, dp2, m);
        dn2 += __shfl_xor_sync(0xFFFFFFFFu, dn2, m);
    }
    if (lane == 0) {
        float loss = fmaxf(sqrtf(dp2) - sqrtf(dn2) + 0.2f, 0.f);
        float corr = 0.f;
        float pxi = px[i], pyi = py[i];
        if (px[nn_st] == pxi && py[nn_st] == pyi) corr += 1.f;
        if (px[nn_ts] == pxi && py[nn_ts] == pyi) corr += 1.f;
        s_loss[warp] = loss;
        s_corr[warp] = corr;
    }
    __syncthreads();
    if (threadIdx.x == 0) {
        float L = 0.f, Cr = 0.f;
        #pragma unroll
        for (int w = 0; w < 8; w++) { L += s_loss[w]; Cr += s_corr[w]; }
        atomicAdd(&g_acc[0], L);
        atomicAdd(&g_acc[1], Cr);
    }
}

// ---------------- 6. write outputs ----------------
__global__ void writeout_kernel(float* __restrict__ out) {
    out[0] = g_acc[0] / (float)(BB*NN);
    out[1] = g_acc[1] / (float)(2*BB*NN);
}

// ---------------- launch ----------------
extern "C" void kernel_launch(void* const* d_in, const int* in_sizes, int n_in,
                              void* d_out, int out_size) {
    const float* src = (const float*)d_in[0];
    const float* tgt = (const float*)d_in[1];
    const float* spn = (const float*)d_in[2];
    const float* tpn = (const float*)d_in[3];
    const float* tpu = (const float*)d_in[4];
    const int*   rf  = (const int*)  d_in[5];
    float* out = (float*)d_out;

    const int T2 = 2*BB*CC*NN;
    transpose_kernel<<<(T2 + 255)/256, 256>>>(src, tgt);
    sample_kernel<<<(BB*2*NN)/8, 256>>>(spn, tpn);

    dim3 grid(NTILE, NTILE, BB);
    gemm_reduce_kernel<<<grid, 256>>>(tpu, rf);

    finalize_kernel<<<(BB*NN)/8, 256>>>(tpu);
    writeout_kernel<<<1, 1>>>(out);
}

// round 5
// speedup vs baseline: 1.2989x; 1.1649x over previous
#include <cuda_runtime.h>
#include <cuda_fp16.h>
#include <cstdint>

#define BB 4
#define CC 64
#define HH 48
#define WW 64
#define NN (HH*WW)        // 3072
#define BM 128
#define BN 128
#define NTILE (NN/BM)     // 24
#define LDK 40            // smem row stride in halves (80B = 5*16B, conflict-free)

// ---------------- device scratch ----------------
__device__ float g_srcT[BB*NN*CC];
__device__ float g_tgtT[BB*NN*CC];
__device__ float g_sd[BB*NN*CC];     // f32 descriptors (for finalize)
__device__ float g_td[BB*NN*CC];
__device__ __half g_sdh[BB*NN*CC];   // fp16 split: hi
__device__ __half g_sdl[BB*NN*CC];   // fp16 split: lo = x - hi
__device__ __half g_tdh[BB*NN*CC];
__device__ __half g_tdl[BB*NN*CC];
__device__ unsigned long long g_row_all[BB*NN];
__device__ unsigned long long g_row_un [BB*NN];
__device__ unsigned long long g_col_all[BB*NN];
__device__ unsigned long long g_col_un [BB*NN];
__device__ float g_acc[2];

// ---------------- key packing: argmax(dot), first-index tie-break ----------------
__device__ __forceinline__ unsigned long long make_key(float f, int idx) {
    unsigned u = __float_as_uint(f);
    u = (u & 0x80000000u) ? ~u : (u | 0x80000000u);
    return ((unsigned long long)u << 32) | (unsigned)(0xFFFFFFFFu - (unsigned)idx);
}
__device__ __forceinline__ float key_dot(unsigned long long k) {
    unsigned u = (unsigned)(k >> 32);
    return (u & 0x80000000u) ? __uint_as_float(u ^ 0x80000000u) : __uint_as_float(~u);
}
__device__ __forceinline__ int key_idx(unsigned long long k) {
    return (int)(0xFFFFFFFFu - (unsigned)(k & 0xFFFFFFFFu));
}
__device__ __forceinline__ float dist_from_dot(float d) {
    d = fminf(fmaxf(d, -1.f), 1.f);
    return sqrtf(fmaxf(2.f - 2.f*d, 0.f));
}
__device__ __forceinline__ void ldmatrix_x4(unsigned& r0, unsigned& r1, unsigned& r2,
                                            unsigned& r3, unsigned addr) {
    asm volatile("ldmatrix.sync.aligned.m8n8.x4.shared.b16 {%0,%1,%2,%3}, [%4];"
        : "=r"(r0), "=r"(r1), "=r"(r2), "=r"(r3) : "r"(addr));
}
__device__ __forceinline__ void mma_f16(float* c, unsigned a0, unsigned a1,
                                        unsigned a2, unsigned a3,
                                        unsigned b0, unsigned b1) {
    asm volatile(
        "mma.sync.aligned.m16n8k16.row.col.f32.f16.f16.f32 "
        "{%0,%1,%2,%3}, {%4,%5,%6,%7}, {%8,%9}, {%0,%1,%2,%3};\n"
        : "+f"(c[0]), "+f"(c[1]), "+f"(c[2]), "+f"(c[3])
        : "r"(a0), "r"(a1), "r"(a2), "r"(a3), "r"(b0), "r"(b1));
}

// ---------------- 1. transpose (B,C,H,W) -> (B,H*W,C), fused init ----------------
__global__ void transpose_kernel(const float* __restrict__ src, const float* __restrict__ tgt) {
    const int T = BB*CC*NN;
    int i = blockIdx.x*blockDim.x + threadIdx.x;
    if (i < 2*T) {
        const float* in; float* out;
        int j = i;
        if (j < T) { in = src; out = g_srcT; } else { j -= T; in = tgt; out = g_tgtT; }
        int p = j % NN;
        int c = (j / NN) % CC;
        int b = j / (NN*CC);
        out[((size_t)b*NN + p)*CC + c] = in[j];
    }
    if (i < BB*NN) {
        g_row_all[i] = 0ULL; g_row_un[i] = 0ULL;
        g_col_all[i] = 0ULL; g_col_un[i] = 0ULL;
    }
    if (i < 2) g_acc[i] = 0.f;
}

// ---------------- 2. bilinear sample + normalize + fp16 hi/lo split ----------------
__global__ void sample_kernel(const float* __restrict__ spn, const float* __restrict__ tpn) {
    int gw   = (blockIdx.x*blockDim.x + threadIdx.x) >> 5;
    int lane = threadIdx.x & 31;
    int b    = gw / (2*NN);
    int rem  = gw - b*2*NN;
    int side = rem / NN;
    int p    = rem - side*NN;

    const float* g = (side ? tpn : spn) + ((size_t)b*NN + p)*2;
    float gx = g[0], gy = g[1];
    const float* img = (side ? g_tgtT : g_srcT) + (size_t)b*NN*CC;

    float x = ((gx + 1.f)*WW - 1.f)*0.5f;
    float y = ((gy + 1.f)*HH - 1.f)*0.5f;
    float x0f = floorf(x), y0f = floorf(y);
    int x0 = (int)x0f, y0 = (int)y0f;
    int x1 = x0 + 1,   y1 = y0 + 1;
    float wx1 = x - x0f, wx0 = 1.f - wx1;
    float wy1 = y - y0f, wy0 = 1.f - wy1;

    float v0 = 0.f, v1 = 0.f;
    #define CORNER(XI, YI, WGT) do { \
        if ((XI) >= 0 && (XI) < WW && (YI) >= 0 && (YI) < HH) { \
            const float* q = img + ((size_t)(YI)*WW + (XI))*CC; \
            v0 += (WGT)*q[lane]; v1 += (WGT)*q[lane+32]; \
        } } while(0)
    CORNER(x0, y0, wx0*wy0);
    CORNER(x1, y0, wx1*wy0);
    CORNER(x0, y1, wx0*wy1);
    CORNER(x1, y1, wx1*wy1);
    #undef CORNER

    float ss = v0*v0 + v1*v1;
    #pragma unroll
    for (int m = 16; m; m >>= 1) ss += __shfl_xor_sync(0xFFFFFFFFu, ss, m);
    float inv = 1.f / fmaxf(sqrtf(ss), 1e-12f);

    size_t base = ((size_t)b*NN + p)*CC;
    float* outf   = (side ? g_td  : g_sd ) + base;
    __half* outh  = (side ? g_tdh : g_sdh) + base;
    __half* outl  = (side ? g_tdl : g_sdl) + base;
    float s0 = v0*inv, s1 = v1*inv;
    outf[lane]    = s0;
    outf[lane+32] = s1;
    __half h0 = __float2half_rn(s0);
    __half h1 = __float2half_rn(s1);
    outh[lane]    = h0;
    outh[lane+32] = h1;
    outl[lane]    = __float2half_rn(s0 - __half2float(h0));
    outl[lane+32] = __float2half_rn(s1 - __half2float(h1));
}

// ---------------- 3. FP16x3 tensor-core GEMM + fused argmax reductions ----------------
__global__ void __launch_bounds__(256) gemm_reduce_kernel(const float* __restrict__ tpu,
                                                          const int* __restrict__ rf) {
    __shared__ __align__(16) __half Ah[BM*LDK];
    __shared__ __align__(16) __half Al[BM*LDK];
    __shared__ __align__(16) __half Bh[BN*LDK];
    __shared__ __align__(16) __half Bl[BN*LDK];
    __shared__ float pxr[BM], pyr[BM], pxc[BN], pyc[BN];
    __shared__ unsigned long long s_r_all[BM], s_r_un[BM], s_c_all[BN], s_c_un[BN];

    const int b       = blockIdx.z;
    const int rowBase = blockIdx.y * BM;
    const int colBase = blockIdx.x * BN;
    const int tid     = threadIdx.x;
    const int wid     = tid >> 5;
    const int lane    = tid & 31;
    const int gid     = lane >> 2;
    const int tig     = lane & 3;

    int rv = rf[0];
    float relax = (rv >= 0 && rv < 1000000) ? (float)rv : __int_as_float(rv);

    // warp tiling: 2 warps along M (64 rows), 4 along N (32 cols)
    const int rowW = (wid & 1) * 64;
    const int colW = (wid >> 1) * 32;

    const size_t baseA = ((size_t)b*NN + rowBase)*CC;
    const size_t baseB = ((size_t)b*NN + colBase)*CC;

    if (tid < 128) {
        const float* px = tpu + (size_t)b*2*NN;
        const float* py = px + NN;
        pxr[tid] = px[rowBase + tid]; pyr[tid] = py[rowBase + tid];
        pxc[tid] = px[colBase + tid]; pyc[tid] = py[colBase + tid];
        s_r_all[tid] = 0ULL; s_r_un[tid] = 0ULL;
        s_c_all[tid] = 0ULL; s_c_un[tid] = 0ULL;
    }

    float acc[4][4][4];
    #pragma unroll
    for (int mt = 0; mt < 4; mt++)
        #pragma unroll
        for (int nt = 0; nt < 4; nt++)
            #pragma unroll
            for (int e = 0; e < 4; e++) acc[mt][nt][e] = 0.f;

    // per-lane ldmatrix byte offset: row = lane&15, k-half = lane>>4
    const unsigned Ah_base = (unsigned)__cvta_generic_to_shared(Ah);
    const unsigned Al_base = (unsigned)__cvta_generic_to_shared(Al);
    const unsigned aoff = ((lane & 15)*LDK + (lane >> 4)*8) * 2;

    #pragma unroll
    for (int kc = 0; kc < 2; kc++) {
        __syncthreads();
        // load 4 tiles (Ah, Al, Bh, Bl), each 128 rows x 32 halves, via uint4
        #pragma unroll
        for (int q = 0; q < 8; q++) {
            const int arr = q >> 1;                 // compile-time per unrolled q
            const int id2 = tid + (q & 1)*256;      // 0..511
            const int row = id2 >> 2;
            const int seg = id2 & 3;                // 8 halves each
            const __half* gsrc = (arr == 0) ? (g_sdh + baseA) :
                                 (arr == 1) ? (g_sdl + baseA) :
                                 (arr == 2) ? (g_tdh + baseB) : (g_tdl + baseB);
            __half* sdst = (arr == 0) ? Ah : (arr == 1) ? Al : (arr == 2) ? Bh : Bl;
            uint4 v = *(const uint4*)(gsrc + (size_t)row*CC + kc*32 + seg*8);
            *(uint4*)(sdst + row*LDK + seg*8) = v;
        }
        __syncthreads();

        #pragma unroll
        for (int ks = 0; ks < 2; ks++) {
            const int kk = ks*16;
            // B fragments: [nt][hi/lo][2 regs]
            unsigned bh[4][2], bl[4][2];
            #pragma unroll
            for (int nt = 0; nt < 4; nt++) {
                int col = colW + nt*8 + gid;
                bh[nt][0] = *(const unsigned*)(Bh + col*LDK + kk + 2*tig);
                bh[nt][1] = *(const unsigned*)(Bh + col*LDK + kk + 8 + 2*tig);
                bl[nt][0] = *(const unsigned*)(Bl + col*LDK + kk + 2*tig);
                bl[nt][1] = *(const unsigned*)(Bl + col*LDK + kk + 8 + 2*tig);
            }
            #pragma unroll
            for (int mt = 0; mt < 4; mt++) {
                const unsigned tileoff = ((rowW + mt*16)*LDK + kk) * 2;
                unsigned ah0, ah1, ah2, ah3, al0, al1, al2, al3;
                ldmatrix_x4(ah0, ah1, ah2, ah3, Ah_base + tileoff + aoff);
                ldmatrix_x4(al0, al1, al2, al3, Al_base + tileoff + aoff);
                #pragma unroll
                for (int nt = 0; nt < 4; nt++) {
                    mma_f16(acc[mt][nt], ah0, ah1, ah2, ah3, bh[nt][0], bh[nt][1]);
                    mma_f16(acc[mt][nt], ah0, ah1, ah2, ah3, bl[nt][0], bl[nt][1]);
                    mma_f16(acc[mt][nt], al0, al1, al2, al3, bh[nt][0], bh[nt][1]);
                }
            }
        }
    }

    // ---- epilogue: row-wise (st) argmax ----
    #pragma unroll
    for (int mt = 0; mt < 4; mt++) {
        #pragma unroll
        for (int half = 0; half < 2; half++) {
            int r_loc = rowW + mt*16 + gid + half*8;
            float prx = pxr[r_loc], pry = pyr[r_loc];
            float va = -3.f, vu = -3.f;
            int   ia = 0,    iu = 0;
            #pragma unroll
            for (int nt = 0; nt < 4; nt++) {
                #pragma unroll
                for (int e = 0; e < 2; e++) {
                    int c_loc = colW + nt*8 + tig*2 + e;
                    float v = acc[mt][nt][half*2 + e];
                    int idx = colBase + c_loc;
                    if (v > va) { va = v; ia = idx; }
                    bool m = (fabsf(pxc[c_loc]-prx) <= relax) && (fabsf(pyc[c_loc]-pry) <= relax);
                    if (!m && v > vu) { vu = v; iu = idx; }
                }
            }
            #pragma unroll
            for (int s = 1; s <= 2; s <<= 1) {
                float ov = __shfl_xor_sync(0xFFFFFFFFu, va, s);
                int   oi = __shfl_xor_sync(0xFFFFFFFFu, ia, s);
                if (ov > va || (ov == va && oi < ia)) { va = ov; ia = oi; }
                float ow = __shfl_xor_sync(0xFFFFFFFFu, vu, s);
                int   oj = __shfl_xor_sync(0xFFFFFFFFu, iu, s);
                if (ow > vu || (ow == vu && oj < iu)) { vu = ow; iu = oj; }
            }
            if (tig == 0) {
                atomicMax(&s_r_all[r_loc], make_key(va, ia));
                if (vu > -2.5f) atomicMax(&s_r_un[r_loc], make_key(vu, iu));
            }
        }
    }
    // ---- col-wise (ts) argmax ----
    #pragma unroll
    for (int nt = 0; nt < 4; nt++) {
        #pragma unroll
        for (int e = 0; e < 2; e++) {
            int c_loc = colW + nt*8 + tig*2 + e;
            float pcx = pxc[c_loc], pcy = pyc[c_loc];
            float va = -3.f, vu = -3.f;
            int   ia = 0,    iu = 0;
            #pragma unroll
            for (int mt = 0; mt < 4; mt++) {
                #pragma unroll
                for (int half = 0; half < 2; half++) {
                    int r_loc = rowW + mt*16 + gid + half*8;
                    float v = acc[mt][nt][half*2 + e];
                    int idx = rowBase + r_loc;
                    if (v > va) { va = v; ia = idx; }
                    bool m = (fabsf(pxr[r_loc]-pcx) <= relax) && (fabsf(pyr[r_loc]-pcy) <= relax);
                    if (!m && v > vu) { vu = v; iu = idx; }
                }
            }
            #pragma unroll
            for (int s = 4; s <= 16; s <<= 1) {
                float ov = __shfl_xor_sync(0xFFFFFFFFu, va, s);
                int   oi = __shfl_xor_sync(0xFFFFFFFFu, ia, s);
                if (ov > va || (ov == va && oi < ia)) { va = ov; ia = oi; }
                float ow = __shfl_xor_sync(0xFFFFFFFFu, vu, s);
                int   oj = __shfl_xor_sync(0xFFFFFFFFu, iu, s);
                if (ow > vu || (ow == vu && oj < iu)) { vu = ow; iu = oj; }
            }
            if (gid == 0) {
                atomicMax(&s_c_all[c_loc], make_key(va, ia));
                if (vu > -2.5f) atomicMax(&s_c_un[c_loc], make_key(vu, iu));
            }
        }
    }
    __syncthreads();
    if (tid < 128) {
        atomicMax(&g_row_all[(size_t)b*NN + rowBase + tid], s_r_all[tid]);
        if (s_r_un[tid]) atomicMax(&g_row_un[(size_t)b*NN + rowBase + tid], s_r_un[tid]);
        atomicMax(&g_col_all[(size_t)b*NN + colBase + tid], s_c_all[tid]);
        if (s_c_un[tid]) atomicMax(&g_col_un[(size_t)b*NN + colBase + tid], s_c_un[tid]);
    }
}

// ---------------- 4. triplet loss + recall ----------------
__global__ void finalize_kernel(const float* __restrict__ tpu) {
    __shared__ float s_loss[8], s_corr[8];
    int gw   = (blockIdx.x*blockDim.x + threadIdx.x) >> 5;
    int lane = threadIdx.x & 31;
    int warp = threadIdx.x >> 5;

    int b = gw / NN;
    int i = gw - b*NN;
    const float* px = tpu + (size_t)b*2*NN;
    const float* py = px + NN;
    size_t base = (size_t)b*NN + i;

    unsigned long long kra = g_row_all[base];
    unsigned long long kru = g_row_un [base];
    unsigned long long kca = g_col_all[base];
    unsigned long long kcu = g_col_un [base];

    int nn_st = key_idx(kra);
    int nn_ts = key_idx(kca);
    int neg_st, neg_ts;
    float d_st, d_ts;
    if (kru == 0ULL) { neg_st = 0; d_st = 2.f; }
    else { neg_st = key_idx(kru); d_st = dist_from_dot(key_dot(kru)); }
    if (kcu == 0ULL) { neg_ts = 0; d_ts = 2.f; }
    else { neg_ts = key_idx(kcu); d_ts = dist_from_dot(key_dot(kcu)); }

    bool take_ts = d_ts < d_st;
    const float* a = (take_ts ? g_td : g_sd) + base*CC;
    const float* p = (take_ts ? g_sd : g_td) + base*CC;
    const float* n = take_ts ? (g_sd + ((size_t)b*NN + neg_ts)*CC)
                             : (g_td + ((size_t)b*NN + neg_st)*CC);

    float dp2 = 0.f, dn2 = 0.f;
    #pragma unroll
    for (int c = lane; c < CC; c += 32) {
        float av = a[c];
        float e1 = av - p[c] + 1e-6f; dp2 = fmaf(e1, e1, dp2);
        float e2 = av - n[c] + 1e-6f; dn2 = fmaf(e2, e2, dn2);
    }
    #pragma unroll
    for (int m = 16; m; m >>= 1) {
        dp2 += __shfl_xor_sync(0xFFFFFFFFu, dp2, m);
        dn2 += __shfl_xor_sync(0xFFFFFFFFu, dn2, m);
    }
    if (lane == 0) {
        float loss = fmaxf(sqrtf(dp2) - sqrtf(dn2) + 0.2f, 0.f);
        float corr = 0.f;
        float pxi = px[i], pyi = py[i];
        if (px[nn_st] == pxi && py[nn_st] == pyi) corr += 1.f;
        if (px[nn_ts] == pxi && py[nn_ts] == pyi) corr += 1.f;
        s_loss[warp] = loss;
        s_corr[warp] = corr;
    }
    __syncthreads();
    if (threadIdx.x == 0) {
        float L = 0.f, Cr = 0.f;
        #pragma unroll
        for (int w = 0; w < 8; w++) { L += s_loss[w]; Cr += s_corr[w]; }
        atomicAdd(&g_acc[0], L);
        atomicAdd(&g_acc[1], Cr);
    }
}

// ---------------- 5. write outputs ----------------
__global__ void writeout_kernel(float* __restrict__ out) {
    out[0] = g_acc[0] / (float)(BB*NN);
    out[1] = g_acc[1] / (float)(2*BB*NN);
}

// ---------------- launch ----------------
extern "C" void kernel_launch(void* const* d_in, const int* in_sizes, int n_in,
                              void* d_out, int out_size) {
    const float* src = (const float*)d_in[0];
    const float* tgt = (const float*)d_in[1];
    const float* spn = (const float*)d_in[2];
    const float* tpn = (const float*)d_in[3];
    const float* tpu = (const float*)d_in[4];
    const int*   rf  = (const int*)  d_in[5];
    float* out = (float*)d_out;

    const int T2 = 2*BB*CC*NN;
    transpose_kernel<<<(T2 + 255)/256, 256>>>(src, tgt);
    sample_kernel<<<(BB*2*NN)/8, 256>>>(spn, tpn);

    dim3 grid(NTILE, NTILE, BB);
    gemm_reduce_kernel<<<grid, 256>>>(tpu, rf);

    finalize_kernel<<<(BB*NN)/8, 256>>>(tpu);
    writeout_kernel<<<1, 1>>>(out);
}